// round 7
// baseline (speedup 1.0000x reference)
#include <cuda_runtime.h>

#define BB 16
#define NN 1024
#define MM 12
#define FA 128
#define FO 128

#define ROWS_PER_BLK 128
#define US 132   // sU row stride in floats ([r][k] layout, 128 k + 4 pad)

// Scratch (allocation-free rule: __device__ globals)
__device__ float g_bn3[BB * NN];
__device__ float g_bn6[BB * NN];
__device__ int   g_is64;

// ---------------------------------------------------------------------------
// packed f32x2 helpers
// ---------------------------------------------------------------------------
__device__ __forceinline__ void fma2(unsigned long long& d,
                                     unsigned long long a,
                                     unsigned long long b) {
    asm("fma.rn.f32x2 %0, %1, %2, %0;" : "+l"(d) : "l"(a), "l"(b));
}
__device__ __forceinline__ unsigned long long dup2(float v) {
    unsigned long long r;
    asm("mov.b64 %0, {%1, %1};" : "=l"(r) : "f"(v));
    return r;
}
__device__ __forceinline__ float2 unpack2(unsigned long long v) {
    float2 r;
    asm("mov.b64 {%0, %1}, %2;" : "=f"(r.x), "=f"(r.y) : "l"(v));
    return r;
}

// ---------------------------------------------------------------------------
// Kernel 1 (v3): one warp per TWO (b,n) rows; all 6 LDG.128 issued up front
// (MLP=6) before the dependent shuffle/rcp chains.
// prod_m(x_m / s) == (prod x_m) / s^12.
// ---------------------------------------------------------------------------
__global__ void bond_kernel(const float* __restrict__ bond,
                            const int* __restrict__ adj_raw) {
    // ---- dtype sniff: int64 indices < 1024 have all-zero odd 32-bit words
    if (blockIdx.x == 0 && threadIdx.x < 32) {
        int lane = threadIdx.x;
        bool odd_zero = true;
        #pragma unroll
        for (int j = 0; j < 32; j++) {
            int pair = lane + 32 * j;
            if (adj_raw[2 * pair + 1] != 0) odd_zero = false;
        }
        bool all = __all_sync(0xffffffffu, odd_zero);
        if (lane == 0) g_is64 = all ? 1 : 0;
    }

    int warp = (blockIdx.x * blockDim.x + threadIdx.x) >> 5;
    int lane = threadIdx.x & 31;
    int row0 = warp * 2;
    if (row0 >= BB * NN) return;

    const float4* p0 = (const float4*)(bond + (size_t)row0 * (MM * 32));
    const float4* p1 = p0 + MM * 32 / 4;
    // issue all 6 loads back-to-back
    float4 a0 = p0[lane];
    float4 a1 = p0[lane + 32];
    float4 a2 = p0[lane + 64];
    float4 b0 = p1[lane];
    float4 b1 = p1[lane + 32];
    float4 b2 = p1[lane + 64];

    float qa0 = a0.x*a0.x + a0.y*a0.y + a0.z*a0.z + a0.w*a0.w;
    float qa1 = a1.x*a1.x + a1.y*a1.y + a1.z*a1.z + a1.w*a1.w;
    float qa2 = a2.x*a2.x + a2.y*a2.y + a2.z*a2.z + a2.w*a2.w;
    float qb0 = b0.x*b0.x + b0.y*b0.y + b0.z*b0.z + b0.w*b0.w;
    float qb1 = b1.x*b1.x + b1.y*b1.y + b1.z*b1.z + b1.w*b1.w;
    float qb2 = b2.x*b2.x + b2.y*b2.y + b2.z*b2.z + b2.w*b2.w;

    #pragma unroll
    for (int o = 4; o >= 1; o >>= 1) {
        qa0 += __shfl_xor_sync(0xffffffffu, qa0, o, 8);
        qa1 += __shfl_xor_sync(0xffffffffu, qa1, o, 8);
        qa2 += __shfl_xor_sync(0xffffffffu, qa2, o, 8);
        qb0 += __shfl_xor_sync(0xffffffffu, qb0, o, 8);
        qb1 += __shfl_xor_sync(0xffffffffu, qb1, o, 8);
        qb2 += __shfl_xor_sync(0xffffffffu, qb2, o, 8);
    }
    float xa0 = 1.0f/qa0, xa1 = 1.0f/qa1, xa2 = 1.0f/qa2;
    float xb0 = 1.0f/qb0, xb1 = 1.0f/qb1, xb2 = 1.0f/qb2;

    float sa = xa0 + xa1 + xa2,  pa = xa0 * xa1 * xa2;
    float sb = xb0 + xb1 + xb2,  pb = xb0 * xb1 * xb2;
    sa += __shfl_xor_sync(0xffffffffu, sa, 8);
    sb += __shfl_xor_sync(0xffffffffu, sb, 8);
    sa += __shfl_xor_sync(0xffffffffu, sa, 16);
    sb += __shfl_xor_sync(0xffffffffu, sb, 16);
    pa *= __shfl_xor_sync(0xffffffffu, pa, 8);
    pb *= __shfl_xor_sync(0xffffffffu, pb, 8);
    pa *= __shfl_xor_sync(0xffffffffu, pa, 16);
    pb *= __shfl_xor_sync(0xffffffffu, pb, 16);

    sa = fmaxf(sa, 1e-12f);
    sb = fmaxf(sb, 1e-12f);
    float sa2 = sa*sa, sa4 = sa2*sa2, sa8 = sa4*sa4;
    float sb2 = sb*sb, sb4 = sb2*sb2, sb8 = sb4*sb4;
    if (lane == 0) {
        g_bn3[row0]     = pa / (sa8 * sa4);
        g_bn3[row0 + 1] = pb / (sb8 * sb4);
    }
}

// ---------------------------------------------------------------------------
// Kernel 2: normalize over B (axis 0), invert, normalize over N (axis 1).
// ---------------------------------------------------------------------------
__global__ void norm_kernel() {
    int b = blockIdx.x;
    int n = threadIdx.x;

    float csum = 0.0f;
    #pragma unroll
    for (int bb = 0; bb < BB; bb++) csum += fabsf(g_bn3[bb * NN + n]);
    csum = fmaxf(csum, 1e-12f);

    float bn4 = g_bn3[b * NN + n] / csum;
    float bn5 = 1.0f / bn4;

    float r = fabsf(bn5);
    #pragma unroll
    for (int o = 16; o >= 1; o >>= 1) r += __shfl_xor_sync(0xffffffffu, r, o, 32);

    __shared__ float part[32];
    __shared__ float total;
    int wid = threadIdx.x >> 5, lane = threadIdx.x & 31;
    if (lane == 0) part[wid] = r;
    __syncthreads();
    if (wid == 0) {
        float v = part[lane];
        #pragma unroll
        for (int o = 16; o >= 1; o >>= 1) v += __shfl_xor_sync(0xffffffffu, v, o, 32);
        if (lane == 0) total = fmaxf(v, 1e-12f);
    }
    __syncthreads();

    g_bn6[b * NN + n] = bn5 / total;
}

// ---------------------------------------------------------------------------
// Kernel 3: gather + scale + fp32 GEMM (u @ W + bias, relu)
// Block = 128 rows x 128 cols, 256 threads -> 128 blocks = ONE wave.
// Warp w gathers rows 16w..16w+15 and its Phase-B threads consume exactly
// those rows -> only __syncwarp between phases; warps pipeline independently
// (one warp's L2 gather overlaps another's FFMA2 stream).
// sU layout [r][k] (natural): Phase A stores are conflict-free STS.128,
// Phase B u reads are 2-address broadcast LDS.32.
// ---------------------------------------------------------------------------
__global__ void __launch_bounds__(256)
main_kernel(const float* __restrict__ atom,
            const int* __restrict__ adj,
            const float* __restrict__ W,
            const float* __restrict__ bias,
            float* __restrict__ out) {
    extern __shared__ float smem[];
    float* sW = smem;                    // 128*128 floats = 64 KB (row-major W[k][j])
    float* sU = smem + FA * FO;          // [r=128][k=128+4 pad] = 67.6 KB

    int b   = blockIdx.y;
    int n0  = blockIdx.x * ROWS_PER_BLK;
    int tid = threadIdx.x;
    int stride = g_is64 ? 2 : 1;         // int64 -> read low words, stride 2

    // Load W into smem, coalesced float4
    {
        const float4* Wg = (const float4*)W;
        float4* sW4 = (float4*)sW;
        #pragma unroll
        for (int i = 0; i < (FA * FO) / 4 / 256; i++)
            sW4[tid + i * 256] = Wg[tid + i * 256];
    }
    __syncthreads();   // only for sW visibility; sU is warp-private below

    int wid = tid >> 5, lane = tid & 31;

    // ---- Phase A: warp w builds rows 16w..16w+15 of u, [r][k] layout
    {
        const float* atomB = atom + b * NN * FA;
        #pragma unroll 2
        for (int i = 0; i < 16; i++) {
            int r = wid * 16 + i;
            int n = n0 + r;
            const int* adjr = adj + (size_t)(b * NN + n) * MM * stride;
            float4 a4 = *(const float4*)(atomB + n * FA + lane * 4);
            float sx = 0.f, sy = 0.f, sz = 0.f, sw = 0.f;
            #pragma unroll
            for (int m = 0; m < MM; m++) {
                int idx = adjr[m * stride] & (NN - 1);
                float4 v = *(const float4*)(atomB + idx * FA + lane * 4);
                sx += v.x; sy += v.y; sz += v.z; sw += v.w;
            }
            float sc = g_bn6[b * NN + n];
            const float inv12 = 1.0f / 12.0f;
            float4 u4;
            u4.x = (a4.x + sx * inv12) * sc;
            u4.y = (a4.y + sy * inv12) * sc;
            u4.z = (a4.z + sz * inv12) * sc;
            u4.w = (a4.w + sw * inv12) * sc;
            *(float4*)(sU + (size_t)r * US + lane * 4) = u4;
        }
    }
    __syncwarp();

    // ---- Phase B: 8 rows x (4 col-pairs) per thread, FFMA2
    int ty = tid >> 4;        // 0..15 -> rows [ty*8, ty*8+8)  (warp w: rows 16w..16w+15)
    int tx = tid & 15;        // 0..15 -> cols [tx*8, tx*8+8)
    int r0 = ty * 8;
    int c0 = tx * 8;

    unsigned long long acc[8][4];
    #pragma unroll
    for (int i = 0; i < 8; i++)
        #pragma unroll
        for (int j = 0; j < 4; j++) acc[i][j] = 0ull;

    #pragma unroll 2
    for (int k = 0; k < FA; k++) {
        ulonglong2 wa = *(const ulonglong2*)(sW + k * FO + c0);
        ulonglong2 wb = *(const ulonglong2*)(sW + k * FO + c0 + 4);
        unsigned long long uu[8];
        #pragma unroll
        for (int i = 0; i < 8; i++)
            uu[i] = dup2(sU[(size_t)(r0 + i) * US + k]);
        #pragma unroll
        for (int i = 0; i < 8; i++) {
            fma2(acc[i][0], uu[i], wa.x);
            fma2(acc[i][1], uu[i], wa.y);
            fma2(acc[i][2], uu[i], wb.x);
            fma2(acc[i][3], uu[i], wb.y);
        }
    }

    // Epilogue: bias + relu + float4 stores
    float4 bi0 = *(const float4*)(bias + c0);
    float4 bi1 = *(const float4*)(bias + c0 + 4);

    #pragma unroll
    for (int i = 0; i < 8; i++) {
        int n = n0 + r0 + i;
        float2 p0 = unpack2(acc[i][0]);
        float2 p1 = unpack2(acc[i][1]);
        float2 p2 = unpack2(acc[i][2]);
        float2 p3 = unpack2(acc[i][3]);
        float4 o0, o1;
        o0.x = fmaxf(p0.x + bi0.x, 0.0f);
        o0.y = fmaxf(p0.y + bi0.y, 0.0f);
        o0.z = fmaxf(p1.x + bi0.z, 0.0f);
        o0.w = fmaxf(p1.y + bi0.w, 0.0f);
        o1.x = fmaxf(p2.x + bi1.x, 0.0f);
        o1.y = fmaxf(p2.y + bi1.y, 0.0f);
        o1.z = fmaxf(p3.x + bi1.z, 0.0f);
        o1.w = fmaxf(p3.y + bi1.w, 0.0f);
        float* op = out + (size_t)(b * NN + n) * FO + c0;
        *(float4*)(op)     = o0;
        *(float4*)(op + 4) = o1;
    }
}

// ---------------------------------------------------------------------------
extern "C" void kernel_launch(void* const* d_in, const int* in_sizes, int n_in,
                              void* d_out, int out_size) {
    const float* atom = (const float*)d_in[0];
    const float* bond = (const float*)d_in[1];
    const int*   adj  = (const int*)d_in[2];
    const float* W    = (const float*)d_in[3];
    const float* bias = (const float*)d_in[4];
    float*       out  = (float*)d_out;

    // 2 rows per warp: 8192 warps = 1024 blocks x 8 warps
    bond_kernel<<<1024, 256>>>(bond, adj);
    norm_kernel<<<BB, NN>>>();

    const int smem_bytes = (FA * FO) * 4 + ROWS_PER_BLK * US * 4;  // 64KB + 67.6KB
    cudaFuncSetAttribute(main_kernel, cudaFuncAttributeMaxDynamicSharedMemorySize,
                         smem_bytes);
    main_kernel<<<dim3(NN / ROWS_PER_BLK, BB), 256, smem_bytes>>>(atom, adj, W, bias, out);
}